// round 3
// baseline (speedup 1.0000x reference)
#include <cuda_runtime.h>

#define T_STEPS 256
#define BATCH   64
#define IN_DIM  512
#define HID     1024
#define MDIM    2048
#define NB      128
#define NT      256

// ---------------- static device scratch ----------------
__device__ float g_xh[(size_t)T_STEPS * BATCH * HID];   // x@Wxh + bh      (64 MB)
__device__ float g_h[BATCH * HID];                      // current h_t
__device__ float g_hpart[32 * BATCH * HID];             // h split-K partials (8 MB)
__device__ float g_upart[(size_t)96 * BATCH * MDIM];    // upd split-K partials (50 MB)
__device__ unsigned g_cnt;
__device__ unsigned g_gen;

// ---------------- packed fp32x2 (2x FFMA rate) ----------------
__device__ __forceinline__ unsigned long long pack2(float a) {
    unsigned long long r;
    asm("mov.b64 %0, {%1, %1};" : "=l"(r) : "f"(a));
    return r;
}
__device__ __forceinline__ void ffma2(unsigned long long& c, unsigned long long a, unsigned long long b) {
    asm("fma.rn.f32x2 %0, %1, %2, %0;" : "+l"(c) : "l"(a), "l"(b));
}

// ---------------- grid barrier (all NB blocks co-resident) ----------------
__device__ __forceinline__ void grid_barrier() {
    __threadfence();                       // release this thread's global writes
    __syncthreads();
    if (threadIdx.x == 0) {
        volatile unsigned* vg = &g_gen;
        unsigned old = *vg;
        unsigned prev = atomicAdd(&g_cnt, 1u);
        if (prev == NB - 1) {
            atomicExch(&g_cnt, 0u);
            __threadfence();
            atomicAdd(&g_gen, 1u);
        } else {
            while (*vg == old) { __nanosleep(64); }
        }
    }
    __syncthreads();
}

// ---------------- 64x256 tile compute, 256 threads, 8x8 per thread ----------
// As: [16][68] (As[k][row]); Bs: [16][260] (Bs[k][col])
__device__ __forceinline__ void tile_compute(const float* As, const float* Bs,
                                             int ty, int tx, unsigned long long acc[8][4]) {
#pragma unroll
    for (int kk = 0; kk < 16; kk++) {
        float4 a0 = *(const float4*)(As + kk * 68 + ty * 8);
        float4 a1 = *(const float4*)(As + kk * 68 + ty * 8 + 4);
        const unsigned long long* bp = (const unsigned long long*)(Bs + kk * 260 + tx * 8);
        unsigned long long b0 = bp[0], b1 = bp[1], b2 = bp[2], b3 = bp[3];
        float a_s[8] = {a0.x, a0.y, a0.z, a0.w, a1.x, a1.y, a1.z, a1.w};
#pragma unroll
        for (int r = 0; r < 8; r++) {
            unsigned long long av = pack2(a_s[r]);
            ffma2(acc[r][0], av, b0);
            ffma2(acc[r][1], av, b1);
            ffma2(acc[r][2], av, b2);
            ffma2(acc[r][3], av, b3);
        }
    }
}

// ---------------- prologue: g_xh = x @ Wxh + bh ----------------
// grid (4 colTiles, 256 rowTiles), 256 threads
__global__ __launch_bounds__(256) void xh_kernel(
    const float* __restrict__ X, const float* __restrict__ Wxh, const float* __restrict__ bh)
{
    __shared__ float As[16 * 68];
    __shared__ float Bs[16 * 260];
    const int tid = threadIdx.x;
    const int ty = tid >> 5, tx = tid & 31;
    const int colBase = blockIdx.x * 256;
    const int rowBase = blockIdx.y * 64;

    unsigned long long acc[8][4];
#pragma unroll
    for (int r = 0; r < 8; r++)
#pragma unroll
        for (int c = 0; c < 4; c++) acc[r][c] = 0ULL;

    for (int ch = 0; ch < 32; ch++) {
        int kb = ch << 4;
        {   // A: 64 rows x 16 k, transpose
            int row = tid >> 2, kl = (tid & 3) << 2;
            float4 v = *(const float4*)(X + (size_t)(rowBase + row) * IN_DIM + kb + kl);
            As[(kl + 0) * 68 + row] = v.x; As[(kl + 1) * 68 + row] = v.y;
            As[(kl + 2) * 68 + row] = v.z; As[(kl + 3) * 68 + row] = v.w;
        }
#pragma unroll
        for (int i = 0; i < 4; i++) {   // B: 16 k x 256 cols, direct (k-major source)
            int g = tid + i * 256;
            int kl = g >> 6, col4 = (g & 63) << 2;
            float4 v = *(const float4*)(Wxh + (size_t)(kb + kl) * HID + colBase + col4);
            *(float4*)(Bs + kl * 260 + col4) = v;
        }
        __syncthreads();
        tile_compute(As, Bs, ty, tx, acc);
        __syncthreads();
    }

#pragma unroll
    for (int r = 0; r < 8; r++) {
        int row = rowBase + ty * 8 + r;
        int jg = colBase + tx * 8;
#pragma unroll
        for (int c = 0; c < 4; c++) {
            float2 v = *(float2*)&acc[r][c];
            float2 bb = *(const float2*)(bh + jg + c * 2);
            v.x += bb.x; v.y += bb.y;
            *(float2*)(g_xh + (size_t)row * HID + jg + c * 2) = v;
        }
    }
}

// ---------------- persistent recurrence kernel ----------------
__global__ __launch_bounds__(256, 1) void rnn_persistent(
    const float* __restrict__ m_prev, const float* __restrict__ Wmh,
    const float* __restrict__ Wmm, const float* __restrict__ Whm,
    const float* __restrict__ bm, float* __restrict__ out)
{
    __shared__ float As[16 * 68];
    __shared__ float Bs[16 * 260];
    const int tid = threadIdx.x;
    const int ty = tid >> 5, tx = tid & 31;
    const int bid = blockIdx.x;
    const int ft = bid * NT + tid;          // flat thread id [0, 32768)

    for (int t = 0; t < T_STEPS; t++) {
        const float* mP = t ? (out + (size_t)(t - 1) * BATCH * MDIM) : m_prev;
        int k = t ? min(__ffs(t), 8) : 8;

        // ---------- phase 1: h partials (4 col tiles x 32 K-splits = 128 units) ----------
        {
            const int s = bid & 31, ct = bid >> 5;
            const int kBase = s * 64, colBase = ct * 256;
            unsigned long long acc[8][4];
#pragma unroll
            for (int r = 0; r < 8; r++)
#pragma unroll
                for (int c = 0; c < 4; c++) acc[r][c] = 0ULL;

            for (int ch = 0; ch < 4; ch++) {
                int kb = kBase + (ch << 4);
                {
                    int row = tid >> 2, kl = (tid & 3) << 2;
                    float4 v = *(const float4*)(mP + (size_t)row * MDIM + kb + kl);
                    As[(kl + 0) * 68 + row] = v.x; As[(kl + 1) * 68 + row] = v.y;
                    As[(kl + 2) * 68 + row] = v.z; As[(kl + 3) * 68 + row] = v.w;
                }
#pragma unroll
                for (int i = 0; i < 4; i++) {
                    int g = tid + i * 256;
                    int col = g >> 2, kl = (g & 3) << 2;
                    float4 v = *(const float4*)(Wmh + (size_t)(colBase + col) * MDIM + kb + kl);
                    Bs[(kl + 0) * 260 + col] = v.x; Bs[(kl + 1) * 260 + col] = v.y;
                    Bs[(kl + 2) * 260 + col] = v.z; Bs[(kl + 3) * 260 + col] = v.w;
                }
                __syncthreads();
                tile_compute(As, Bs, ty, tx, acc);
                __syncthreads();
            }
#pragma unroll
            for (int r = 0; r < 8; r++) {
                int row = ty * 8 + r;
                size_t base = (size_t)(s * 64 + row) * HID + colBase + tx * 8;
#pragma unroll
                for (int c = 0; c < 4; c++)
                    *(float2*)(g_hpart + base + c * 2) = *(float2*)&acc[r][c];
            }
        }
        grid_barrier();

        // ---------- phase 2: h = tanh(xh_t + sum_32 partials) ----------
        if (ft < 16384) {
            size_t off = (size_t)ft * 4;
            float4 s4 = *(const float4*)(g_xh + (size_t)t * BATCH * HID + off);
#pragma unroll 8
            for (int p = 0; p < 32; p++) {
                float4 v = __ldcg((const float4*)(g_hpart + (size_t)p * BATCH * HID + off));
                s4.x += v.x; s4.y += v.y; s4.z += v.z; s4.w += v.w;
            }
            float4 o = make_float4(tanhf(s4.x), tanhf(s4.y), tanhf(s4.z), tanhf(s4.w));
            *(float4*)(g_h + off) = o;
        }
        grid_barrier();

        // ---------- phase 3: upd partials (k col tiles x 96 K-splits) ----------
        for (int u = bid; u < 96 * k; u += NB) {
            const int ct = u / 96, s = u % 96;
            const int kBase = s * 32, colBase = ct * 256;
            unsigned long long acc[8][4];
#pragma unroll
            for (int r = 0; r < 8; r++)
#pragma unroll
                for (int c = 0; c < 4; c++) acc[r][c] = 0ULL;

            for (int ch = 0; ch < 2; ch++) {
                int kb = kBase + (ch << 4);
                {
                    int row = tid >> 2, kl = (tid & 3) << 2;
                    float4 v;
                    if (kb < MDIM) v = *(const float4*)(mP + (size_t)row * MDIM + kb + kl);
                    else           v = __ldcg((const float4*)(g_h + (size_t)row * HID + (kb - MDIM) + kl));
                    As[(kl + 0) * 68 + row] = v.x; As[(kl + 1) * 68 + row] = v.y;
                    As[(kl + 2) * 68 + row] = v.z; As[(kl + 3) * 68 + row] = v.w;
                }
#pragma unroll
                for (int i = 0; i < 4; i++) {
                    int g = tid + i * 256;
                    int col = g >> 2, kl = (g & 3) << 2;
                    int jg = colBase + col;
                    float4 v;
                    if (kb < MDIM) v = *(const float4*)(Wmm + (size_t)jg * MDIM + kb + kl);
                    else           v = *(const float4*)(Whm + (size_t)jg * HID + (kb - MDIM) + kl);
                    Bs[(kl + 0) * 260 + col] = v.x; Bs[(kl + 1) * 260 + col] = v.y;
                    Bs[(kl + 2) * 260 + col] = v.z; Bs[(kl + 3) * 260 + col] = v.w;
                }
                __syncthreads();
                tile_compute(As, Bs, ty, tx, acc);
                __syncthreads();
            }
#pragma unroll
            for (int r = 0; r < 8; r++) {
                int row = ty * 8 + r;
                size_t base = (size_t)(s * 64 + row) * MDIM + colBase + tx * 8;
#pragma unroll
                for (int c = 0; c < 4; c++)
                    *(float2*)(g_upart + base + c * 2) = *(float2*)&acc[r][c];
            }
        }
        grid_barrier();

        // ---------- phase 4: out[t] = clockwork merge(bm + sum_96 partials, m_prev) ----------
        {
            int b = ft >> 9;
            int j = (ft & 511) << 2;
            int ac = k << 8;
            float4 v;
            if (j < ac) {
                v = *(const float4*)(bm + j);
#pragma unroll 8
                for (int p = 0; p < 96; p++) {
                    float4 w = __ldcg((const float4*)(g_upart + (size_t)p * BATCH * MDIM + (size_t)b * MDIM + j));
                    v.x += w.x; v.y += w.y; v.z += w.z; v.w += w.w;
                }
            } else {
                v = *(const float4*)(mP + (size_t)b * MDIM + j);
            }
            *(float4*)(out + (size_t)t * BATCH * MDIM + (size_t)b * MDIM + j) = v;
            if (t == T_STEPS - 1)
                *(float4*)(out + (size_t)T_STEPS * BATCH * MDIM + (size_t)b * MDIM + j) = v;
        }
        grid_barrier();
    }
}

// ---------------- host ----------------
extern "C" void kernel_launch(void* const* d_in, const int* in_sizes, int n_in,
                              void* d_out, int out_size)
{
    const float* x      = (const float*)d_in[0];
    const float* m_prev = (const float*)d_in[1];
    const float* Wxh    = (const float*)d_in[2];
    const float* Whm    = (const float*)d_in[3];
    const float* Wmm    = (const float*)d_in[4];
    const float* Wmh    = (const float*)d_in[5];
    const float* bm     = (const float*)d_in[6];
    const float* bh     = (const float*)d_in[7];
    float* out = (float*)d_out;
    (void)in_sizes; (void)n_in; (void)out_size;

    xh_kernel<<<dim3(4, 256), 256>>>(x, Wxh, bh);
    rnn_persistent<<<NB, NT>>>(m_prev, Wmh, Wmm, Whm, bm, out);
}